// round 6
// baseline (speedup 1.0000x reference)
#include <cuda_runtime.h>

#define Bn 4
#define Cn 3
#define Zd 64
#define Hd 192
#define Wd 192
#define BC (Bn*Cn)
#define VOX (Zd*Hd*Wd)        /* 2359296 */
#define WPR (Wd/32)           /* 6 u32 words per (z,h) row of bits */

// Scratch (static device arrays: allocation-free; accumulators zeroed at load
// and re-zeroed by finalize() so graph replays are deterministic).
__device__ unsigned int g_tsb[(size_t)BC * VOX / 32];  // bit-packed ts, 3.5 MB
__device__ double       g_pm[BC];                      // sum(p*m)
__device__ double       g_p [BC];                      // sum(p)
__device__ unsigned int g_m [BC];                      // count(m==1)
__device__ unsigned int g_eq[BC];                      // count(ts==m)
__device__ unsigned int g_ed[BC];                      // count(grad>0)

// ---------------------------------------------------------------------------
// Pass 1: stream output+masks once (perfectly coalesced: lane-consecutive
// float4s), emit bit-packed ts via a shared-memory nibble staging buffer.
// grid = (576, 12), 256 thr; block covers 4096 consecutive voxels
// (1024 float4s = 4 iters x 256 threads). 576*4096 = VOX exactly.
// Bit layout: global bit index == voxel index (little-endian throughout).
// ---------------------------------------------------------------------------
__global__ __launch_bounds__(256) void pass1(const float* __restrict__ outp,
                                             const float* __restrict__ mskp,
                                             const float* __restrict__ thr_p) {
    const float thr = *thr_p;
    const int bc = blockIdx.y;
    const size_t base = (size_t)bc * VOX;
    const float4* __restrict__ o4 = (const float4*)(outp + base);
    const float4* __restrict__ m4 = (const float4*)(mskp + base);
    unsigned int* __restrict__ tsw =
        g_tsb + (size_t)bc * (VOX / 32) + blockIdx.x * 128;

    const int tid = threadIdx.x;
    const int blockstart = blockIdx.x * 1024;   // float4 index of block base

    __shared__ unsigned int s_nib[1024];        // one 4-bit nibble per float4

    float pm = 0.f, ps = 0.f;
    unsigned int mc = 0u, eqc = 0u;

#pragma unroll
    for (int i = 0; i < 4; i++) {
        int local = i * 256 + tid;              // float4 index within block
        int idx = blockstart + local;
        float4 p = o4[idx];
        float4 m = m4[idx];
        unsigned t0 = p.x > thr;
        unsigned t1 = p.y > thr;
        unsigned t2 = p.z > thr;
        unsigned t3 = p.w > thr;
        s_nib[local] = t0 | (t1 << 1) | (t2 << 2) | (t3 << 3);
        pm += p.x * m.x + p.y * m.y + p.z * m.z + p.w * m.w;
        ps += p.x + p.y + p.z + p.w;
        unsigned b0 = m.x != 0.f, b1 = m.y != 0.f, b2 = m.z != 0.f, b3 = m.w != 0.f;
        mc  += b0 + b1 + b2 + b3;
        eqc += (t0 == b0) + (t1 == b1) + (t2 == b2) + (t3 == b3);
    }
    __syncthreads();

    // Assemble 8 nibbles -> one u32 word; word t covers voxels 32t..32t+31
    // of this block => global bit index == voxel index. Coalesced 512B store.
    if (tid < 128) {
        unsigned int wrd = 0u;
#pragma unroll
        for (int j = 0; j < 8; j++)
            wrd |= s_nib[8 * tid + j] << (4 * j);
        tsw[tid] = wrd;
    }

    // warp reduce
#pragma unroll
    for (int o = 16; o; o >>= 1) {
        pm  += __shfl_down_sync(0xffffffffu, pm,  o);
        ps  += __shfl_down_sync(0xffffffffu, ps,  o);
        mc  += __shfl_down_sync(0xffffffffu, mc,  o);
        eqc += __shfl_down_sync(0xffffffffu, eqc, o);
    }
    __shared__ float    s_pm[8], s_ps[8];
    __shared__ unsigned s_mc[8], s_eq[8];
    int w = tid >> 5, l = tid & 31;
    if (l == 0) { s_pm[w] = pm; s_ps[w] = ps; s_mc[w] = mc; s_eq[w] = eqc; }
    __syncthreads();
    if (tid == 0) {
#pragma unroll
        for (int i = 1; i < 8; i++) { pm += s_pm[i]; ps += s_ps[i]; mc += s_mc[i]; eqc += s_eq[i]; }
        atomicAdd(&g_pm[bc], (double)pm);
        atomicAdd(&g_p [bc], (double)ps);
        atomicAdd(&g_m [bc], mc);
        atomicAdd(&g_eq[bc], eqc);
    }
}

// ---------------------------------------------------------------------------
// Pass 2: sobel edge count on bit-packed ts.
// grid = (192 h, 12 bc), 192 threads (one per w).
// s(z,h,w) = sum_{dz,dh in [-1,1]} wz*wh * ts  (weights 1,2,1; symmetric reflect)
// grad(w)  = s(w+1) - s(w-1), clamped indices at w edges (matches scipy reflect)
// Rows are word-aligned (Wd=192 = 6*32); bit extraction via broadcast u32 loads.
// ---------------------------------------------------------------------------
__global__ __launch_bounds__(192) void pass2() {
    const int bc = blockIdx.y;
    const int h  = blockIdx.x;
    const int w  = threadIdx.x;
    const unsigned int* __restrict__ ts = g_tsb + (size_t)bc * (VOX / 32);

    const int hm = (h > 0)      ? h - 1 : 0;
    const int hp = (h < Hd - 1) ? h + 1 : Hd - 1;
    const int wm = (w > 0)      ? w - 1 : 0;
    const int wp = (w < Wd - 1) ? w + 1 : Wd - 1;

    const int wword = w >> 5;
    const int wbit  = w & 31;

    __shared__ int s_sh[Wd];

    // hs(z) = h-smoothed bit value at (z, w): bit(hm) + 2*bit(h) + bit(hp)
    auto HS = [&](int z) -> int {
        const unsigned int* r = ts + (size_t)z * Hd * WPR;
        unsigned am = r[hm * WPR + wword];
        unsigned bm = r[h  * WPR + wword];
        unsigned cm = r[hp * WPR + wword];
        return (int)((am >> wbit) & 1u) + 2 * (int)((bm >> wbit) & 1u)
             + (int)((cm >> wbit) & 1u);
    };

    int b = HS(0);
    int a = b;          // z reflect at front
    int c = HS(1);
    unsigned cnt = 0;

    for (int z = 0; z < Zd; z++) {
        int s = a + 2 * b + c;
        s_sh[w] = s;
        __syncthreads();
        int grad = s_sh[wp] - s_sh[wm];
        cnt += (grad > 0);
        __syncthreads();
        a = b; b = c;
        int zn = z + 2; if (zn > Zd - 1) zn = Zd - 1;   // z reflect at back
        c = HS(zn);
    }

#pragma unroll
    for (int o = 16; o; o >>= 1) cnt += __shfl_down_sync(0xffffffffu, cnt, o);
    __shared__ unsigned s_c[6];
    int wid = threadIdx.x >> 5, l = threadIdx.x & 31;
    if (l == 0) s_c[wid] = cnt;
    __syncthreads();
    if (threadIdx.x == 0) {
        unsigned t = 0;
#pragma unroll
        for (int i = 0; i < 6; i++) t += s_c[i];
        atomicAdd(&g_ed[bc], t);
    }
}

// ---------------------------------------------------------------------------
// Pass 3: finalize (tiny) + reset accumulators for the next graph replay.
// ---------------------------------------------------------------------------
__global__ void finalize(float* __restrict__ outp) {
    if (threadIdx.x != 0) return;
    double loss = 0.0;
    for (int b = 0; b < Bn; b++) {
        double f[Cn];
        for (int c = 0; c < Cn; c++) f[c] = (double)g_m[b * Cn + c] / (double)VOX;
        double mn = fmin(f[0], fmin(f[1], f[2]));
        double mx = fmax(f[0], fmax(f[1], f[2]));
        double med = f[0] + f[1] + f[2] - mn - mx;   // median of 3
        double w0 = 2.0 * med / (mn + 1e-05);
        double nom = 0.0, den = 0.0;
        for (int c = 0; c < Cn; c++) {
            int i = b * Cn + c;
            double cw = (double)g_eq[i] * med / (f[c] + 1e-05) + w0 * (double)g_ed[i];
            double p1 = g_pm[i];
            double p2 = g_p[i] + (double)g_m[i];
            nom += cw * p1;
            den += cw * p2 + 1e-07;
        }
        loss += 1.0 - 2.0 * nom / den;
    }
    outp[0] = (float)(loss / (double)Bn);

    // reset for next replay (deterministic across graph launches)
#pragma unroll
    for (int i = 0; i < BC; i++) {
        g_pm[i] = 0.0; g_p[i] = 0.0; g_m[i] = 0u; g_eq[i] = 0u; g_ed[i] = 0u;
    }
}

extern "C" void kernel_launch(void* const* d_in, const int* in_sizes, int n_in,
                              void* d_out, int out_size) {
    const float* outp = (const float*)d_in[0];
    const float* mskp = (const float*)d_in[1];
    const float* thr  = (const float*)d_in[2];
    float* res = (float*)d_out;

    pass1<<<dim3(576, BC), 256>>>(outp, mskp, thr);
    pass2<<<dim3(Hd, BC), 192>>>();
    finalize<<<1, 1>>>(res);
}

// round 15
// speedup vs baseline: 2.1415x; 2.1415x over previous
#include <cuda_runtime.h>

#define Bn 4
#define Cn 3
#define Zd 64
#define Hd 192
#define Wd 192
#define BC (Bn*Cn)
#define VOX (Zd*Hd*Wd)        /* 2359296 */
#define WPR (Wd/32)           /* 6 u32 words per (z,h) row of bits */
#define P2_BLOCKS (24*BC)     /* 288 pass2 blocks */

// Scratch (static device arrays: allocation-free; zero-init at load; the
// pass2 finalize block re-zeroes everything so graph replays are deterministic).
__device__ unsigned int g_tsb[(size_t)BC * VOX / 32];  // bit-packed ts, 3.5 MB
__device__ double       g_pm[BC];                      // sum(p*m)
__device__ double       g_p [BC];                      // sum(p)
__device__ unsigned int g_m [BC];                      // count(m==1)
__device__ unsigned int g_eq[BC];                      // count(ts==m)
__device__ unsigned int g_ed[BC];                      // count(grad>0)
__device__ unsigned int g_ticket;                      // pass2 completion ticket

// ---------------------------------------------------------------------------
// Pass 1: stream output+masks once (coalesced lane-consecutive float4s,
// streaming loads), emit bit-packed ts via shared-memory nibble staging.
// grid = (576, 12), 256 thr; block covers 4096 consecutive voxels.
// Bit layout: global bit index == voxel index (little-endian).
// ---------------------------------------------------------------------------
__global__ __launch_bounds__(256) void pass1(const float* __restrict__ outp,
                                             const float* __restrict__ mskp,
                                             const float* __restrict__ thr_p) {
    const float thr = *thr_p;
    const int bc = blockIdx.y;
    const size_t base = (size_t)bc * VOX;
    const float4* __restrict__ o4 = (const float4*)(outp + base);
    const float4* __restrict__ m4 = (const float4*)(mskp + base);
    unsigned int* __restrict__ tsw =
        g_tsb + (size_t)bc * (VOX / 32) + blockIdx.x * 128;

    const int tid = threadIdx.x;
    const int blockstart = blockIdx.x * 1024;   // float4 index of block base

    __shared__ unsigned int s_nib[1024];        // one 4-bit nibble per float4

    float pm = 0.f, ps = 0.f;
    unsigned int mc = 0u, eqc = 0u;

#pragma unroll
    for (int i = 0; i < 4; i++) {
        int local = i * 256 + tid;
        int idx = blockstart + local;
        float4 p = __ldcs(&o4[idx]);
        float4 m = __ldcs(&m4[idx]);
        unsigned t0 = p.x > thr;
        unsigned t1 = p.y > thr;
        unsigned t2 = p.z > thr;
        unsigned t3 = p.w > thr;
        s_nib[local] = t0 | (t1 << 1) | (t2 << 2) | (t3 << 3);
        pm += p.x * m.x + p.y * m.y + p.z * m.z + p.w * m.w;
        ps += p.x + p.y + p.z + p.w;
        unsigned b0 = m.x != 0.f, b1 = m.y != 0.f, b2 = m.z != 0.f, b3 = m.w != 0.f;
        mc  += b0 + b1 + b2 + b3;
        eqc += (t0 == b0) + (t1 == b1) + (t2 == b2) + (t3 == b3);
    }
    __syncthreads();

    // 8 nibbles -> one u32 word; coalesced 512B store per block.
    if (tid < 128) {
        unsigned int wrd = 0u;
#pragma unroll
        for (int j = 0; j < 8; j++)
            wrd |= s_nib[8 * tid + j] << (4 * j);
        tsw[tid] = wrd;
    }

#pragma unroll
    for (int o = 16; o; o >>= 1) {
        pm  += __shfl_down_sync(0xffffffffu, pm,  o);
        ps  += __shfl_down_sync(0xffffffffu, ps,  o);
        mc  += __shfl_down_sync(0xffffffffu, mc,  o);
        eqc += __shfl_down_sync(0xffffffffu, eqc, o);
    }
    __shared__ float    s_pm[8], s_ps[8];
    __shared__ unsigned s_mc[8], s_eq[8];
    int w = tid >> 5, l = tid & 31;
    if (l == 0) { s_pm[w] = pm; s_ps[w] = ps; s_mc[w] = mc; s_eq[w] = eqc; }
    __syncthreads();
    if (tid == 0) {
#pragma unroll
        for (int i = 1; i < 8; i++) { pm += s_pm[i]; ps += s_ps[i]; mc += s_mc[i]; eqc += s_eq[i]; }
        atomicAdd(&g_pm[bc], (double)pm);
        atomicAdd(&g_p [bc], (double)ps);
        atomicAdd(&g_m [bc], mc);
        atomicAdd(&g_eq[bc], eqc);
    }
}

// ---------------------------------------------------------------------------
// Pass 2: bit-sliced sobel edge count + fused finalize (threadfence ticket).
// grid = (24, 12): blockIdx.x = hg*4 + zc  (6 h-groups of 32, 4 z-chunks of 16)
// 192 threads: tid = hl*6 + ww  (hl = h within group, ww = word 0..5).
// Each thread processes 32 w-positions (one word) via bit-plane arithmetic:
//   h-smooth a+2b+c of 3 bit-rows -> 3 planes (max 4)
//   z-smooth A+2B+C of plane triplets -> 5 planes S (max 16)
//   grad(w) = S(w+1) - S(w-1) > 0 via bit-sliced 5-bit compare; popc counts.
// Word-boundary neighbor values carried as scalar zsum side-channels.
// Reflect boundaries = index clamping (radius-1 symmetric pad).
// The last block to finish (ticket==P2_BLOCKS-1) computes the loss, writes
// d_out, and resets all accumulators + ticket (graph-replay deterministic).
// ---------------------------------------------------------------------------
__global__ __launch_bounds__(192) void pass2(float* __restrict__ res) {
    const int bc = blockIdx.y;
    const int hg = blockIdx.x >> 2;       // 0..5
    const int zc = blockIdx.x & 3;        // 0..3
    const int tid = threadIdx.x;
    const int ww = tid % 6;
    const int hl = tid / 6;               // 0..31
    const int h  = hg * 32 + hl;
    const unsigned int* __restrict__ ts = g_tsb + (size_t)bc * (VOX / 32);

    const int hm = (h > 0)      ? h - 1 : 0;
    const int hp = (h < Hd - 1) ? h + 1 : Hd - 1;
    const int om = hm * WPR + ww, oh = h * WPR + ww, op = hp * WPR + ww;
    const bool hasL = (ww > 0), hasR = (ww < 5);

    // h-smoothed planes + scalar boundary zsum inputs for row z
    auto planes = [&](int z, unsigned& p0, unsigned& p1, unsigned& p2,
                      int& sl, int& sr) {
        const unsigned int* r = ts + (size_t)z * (Hd * WPR);
        unsigned a = r[om], b = r[oh], c = r[op];
        unsigned q = a & c;
        p0 = a ^ c;          // a + 2b + c  bit-sliced (max 4)
        p1 = q ^ b;
        p2 = q & b;
        if (hasL) {          // h-smoothed value at bit31 of word ww-1
            unsigned la = r[om - 1], lb = r[oh - 1], lc = r[op - 1];
            sl = (int)(la >> 31) + 2 * (int)(lb >> 31) + (int)(lc >> 31);
        } else sl = 0;
        if (hasR) {          // h-smoothed value at bit0 of word ww+1
            unsigned ra = r[om + 1], rb = r[oh + 1], rc = r[op + 1];
            sr = (int)(ra & 1u) + 2 * (int)(rb & 1u) + (int)(rc & 1u);
        } else sr = 0;
    };

    const int z0 = zc * 16;
    unsigned A0, A1, A2, B0, B1, B2, C0, C1, C2;
    int aL, aR, bL, bR, cL, cR;
    planes((z0 > 0) ? z0 - 1 : 0, A0, A1, A2, aL, aR);
    planes(z0,                    B0, B1, B2, bL, bR);
    planes(z0 + 1,                C0, C1, C2, cL, cR);   // z0<=48 -> z0+1<=49

    unsigned cnt = 0;

    for (int i = 0; i < 16; i++) {
        const int z = z0 + i;
        // S = A + 2B + C  (bit-sliced, 5 planes, max 16)
        unsigned k, t0, t1, t2, t3, S0, S1, S2, S3, S4;
        t0 = A0 ^ C0;              k = A0 & C0;
        t1 = A1 ^ C1 ^ k;          k = (A1 & C1) | (k & (A1 ^ C1));
        t2 = A2 ^ C2 ^ k;          k = (A2 & C2) | (k & (A2 ^ C2));
        t3 = k;
        S0 = t0;
        S1 = t1 ^ B0;              k = t1 & B0;
        S2 = t2 ^ B1 ^ k;          k = (t2 & B1) | (k & (t2 ^ B1));
        S3 = t3 ^ B2 ^ k;          k = (t3 & B2) | (k & (t3 ^ B2));
        S4 = k;
        // scalar boundary zsums
        const int SL = aL + 2 * bL + cL;   // zsum at bit31 of word ww-1
        const int SR = aR + 2 * bR + cR;   // zsum at bit0  of word ww+1

        // X = S at w+1, Y = S at w-1 (per bit position)
        unsigned X0, X1, X2, X3, X4, Y0, Y1, Y2, Y3, Y4;
        if (hasR) {
            X0 = (S0 >> 1) | (((unsigned)(SR      & 1)) << 31);
            X1 = (S1 >> 1) | (((unsigned)((SR >> 1) & 1)) << 31);
            X2 = (S2 >> 1) | (((unsigned)((SR >> 2) & 1)) << 31);
            X3 = (S3 >> 1) | (((unsigned)((SR >> 3) & 1)) << 31);
            X4 = (S4 >> 1) | (((unsigned)((SR >> 4) & 1)) << 31);
        } else {   // global right edge: wp clamps to 191 (own bit 31)
            X0 = (S0 >> 1) | (S0 & 0x80000000u);
            X1 = (S1 >> 1) | (S1 & 0x80000000u);
            X2 = (S2 >> 1) | (S2 & 0x80000000u);
            X3 = (S3 >> 1) | (S3 & 0x80000000u);
            X4 = (S4 >> 1) | (S4 & 0x80000000u);
        }
        if (hasL) {
            Y0 = (S0 << 1) | ((unsigned)(SL      & 1));
            Y1 = (S1 << 1) | ((unsigned)((SL >> 1) & 1));
            Y2 = (S2 << 1) | ((unsigned)((SL >> 2) & 1));
            Y3 = (S3 << 1) | ((unsigned)((SL >> 3) & 1));
            Y4 = (S4 << 1) | ((unsigned)((SL >> 4) & 1));
        } else {   // global left edge: wm clamps to 0 (own bit 0)
            Y0 = (S0 << 1) | (S0 & 1u);
            Y1 = (S1 << 1) | (S1 & 1u);
            Y2 = (S2 << 1) | (S2 & 1u);
            Y3 = (S3 << 1) | (S3 & 1u);
            Y4 = (S4 << 1) | (S4 & 1u);
        }

        // bit-sliced 5-bit compare: g = (X > Y) per position
        unsigned e, g;
        e = ~(X4 ^ Y4);            g = X4 & ~Y4;
        g |= e & (X3 & ~Y3);       e &= ~(X3 ^ Y3);
        g |= e & (X2 & ~Y2);       e &= ~(X2 ^ Y2);
        g |= e & (X1 & ~Y1);       e &= ~(X1 ^ Y1);
        g |= e & (X0 & ~Y0);
        cnt += __popc(g);

        // roll z-window, fetch row z+2 (clamped = symmetric reflect at back)
        A0 = B0; A1 = B1; A2 = B2; aL = bL; aR = bR;
        B0 = C0; B1 = C1; B2 = C2; bL = cL; bR = cR;
        int zn = z + 2; if (zn > Zd - 1) zn = Zd - 1;
        planes(zn, C0, C1, C2, cL, cR);
    }

#pragma unroll
    for (int o = 16; o; o >>= 1) cnt += __shfl_down_sync(0xffffffffu, cnt, o);
    __shared__ unsigned s_c[6];
    int wid = tid >> 5, l = tid & 31;
    if (l == 0) s_c[wid] = cnt;
    __syncthreads();

    // Block contribution + completion ticket. Last block finalizes.
    __shared__ bool s_last;
    if (tid == 0) {
        unsigned t = 0;
#pragma unroll
        for (int i = 0; i < 6; i++) t += s_c[i];
        atomicAdd(&g_ed[bc], t);
        __threadfence();                           // order g_ed before ticket
        unsigned rank = atomicAdd(&g_ticket, 1u);
        s_last = (rank == P2_BLOCKS - 1);
    }
    __syncthreads();
    if (!s_last || tid != 0) return;

    // ---- finalize (single thread of the last block) ----
    __threadfence();                               // acquire all g_* writes
    double loss = 0.0;
    for (int b = 0; b < Bn; b++) {
        double f[Cn];
        for (int c = 0; c < Cn; c++) f[c] = (double)g_m[b * Cn + c] / (double)VOX;
        double mn = fmin(f[0], fmin(f[1], f[2]));
        double mx = fmax(f[0], fmax(f[1], f[2]));
        double med = f[0] + f[1] + f[2] - mn - mx;   // median of 3
        double w0 = 2.0 * med / (mn + 1e-05);
        double nom = 0.0, den = 0.0;
        for (int c = 0; c < Cn; c++) {
            int i = b * Cn + c;
            double cw = (double)g_eq[i] * med / (f[c] + 1e-05) + w0 * (double)g_ed[i];
            double p1 = g_pm[i];
            double p2 = g_p[i] + (double)g_m[i];
            nom += cw * p1;
            den += cw * p2 + 1e-07;
        }
        loss += 1.0 - 2.0 * nom / den;
    }
    res[0] = (float)(loss / (double)Bn);

    // reset for next graph replay (deterministic)
#pragma unroll
    for (int i = 0; i < BC; i++) {
        g_pm[i] = 0.0; g_p[i] = 0.0; g_m[i] = 0u; g_eq[i] = 0u; g_ed[i] = 0u;
    }
    g_ticket = 0u;
}

extern "C" void kernel_launch(void* const* d_in, const int* in_sizes, int n_in,
                              void* d_out, int out_size) {
    const float* outp = (const float*)d_in[0];
    const float* mskp = (const float*)d_in[1];
    const float* thr  = (const float*)d_in[2];
    float* res = (float*)d_out;

    pass1<<<dim3(576, BC), 256>>>(outp, mskp, thr);
    pass2<<<dim3(24, BC), 192>>>(res);
}

// round 16
// speedup vs baseline: 2.2135x; 1.0336x over previous
#include <cuda_runtime.h>

#define Bn 4
#define Cn 3
#define Zd 64
#define Hd 192
#define Wd 192
#define BC (Bn*Cn)
#define VOX (Zd*Hd*Wd)        /* 2359296 */
#define WPR (Wd/32)           /* 6 u32 words per (z,h) row of bits */
#define ZCH 8                 /* z-rows per pass2 block */
#define P2_BLOCKS (48*BC)     /* 576 pass2 blocks */

// Scratch (static device arrays: allocation-free; zero-init at load; the
// pass2 finalize block re-zeroes everything so graph replays are deterministic).
__device__ unsigned int g_tsb[(size_t)BC * VOX / 32];  // bit-packed ts, 3.5 MB
__device__ double       g_pm[BC];                      // sum(p*m)
__device__ double       g_p [BC];                      // sum(p)
__device__ unsigned int g_m [BC];                      // count(m==1)
__device__ unsigned int g_eq[BC];                      // count(ts==m)
__device__ unsigned int g_ed[BC];                      // count(grad>0)
__device__ unsigned int g_ticket;                      // pass2 completion ticket

// ---------------------------------------------------------------------------
// Pass 1: stream output+masks once (coalesced lane-consecutive float4s,
// streaming loads), emit bit-packed ts via shared-memory nibble staging.
// grid = (576, 12), 256 thr; block covers 4096 consecutive voxels.
// Bit layout: global bit index == voxel index (little-endian).
// ---------------------------------------------------------------------------
__global__ __launch_bounds__(256) void pass1(const float* __restrict__ outp,
                                             const float* __restrict__ mskp,
                                             const float* __restrict__ thr_p) {
    const float thr = *thr_p;
    const int bc = blockIdx.y;
    const size_t base = (size_t)bc * VOX;
    const float4* __restrict__ o4 = (const float4*)(outp + base);
    const float4* __restrict__ m4 = (const float4*)(mskp + base);
    unsigned int* __restrict__ tsw =
        g_tsb + (size_t)bc * (VOX / 32) + blockIdx.x * 128;

    const int tid = threadIdx.x;
    const int blockstart = blockIdx.x * 1024;   // float4 index of block base

    __shared__ unsigned int s_nib[1024];        // one 4-bit nibble per float4

    float pm = 0.f, ps = 0.f;
    unsigned int mc = 0u, eqc = 0u;

#pragma unroll
    for (int i = 0; i < 4; i++) {
        int local = i * 256 + tid;
        int idx = blockstart + local;
        float4 p = __ldcs(&o4[idx]);
        float4 m = __ldcs(&m4[idx]);
        unsigned t0 = p.x > thr;
        unsigned t1 = p.y > thr;
        unsigned t2 = p.z > thr;
        unsigned t3 = p.w > thr;
        s_nib[local] = t0 | (t1 << 1) | (t2 << 2) | (t3 << 3);
        pm += p.x * m.x + p.y * m.y + p.z * m.z + p.w * m.w;
        ps += p.x + p.y + p.z + p.w;
        unsigned b0 = m.x != 0.f, b1 = m.y != 0.f, b2 = m.z != 0.f, b3 = m.w != 0.f;
        mc  += b0 + b1 + b2 + b3;
        eqc += (t0 == b0) + (t1 == b1) + (t2 == b2) + (t3 == b3);
    }
    __syncthreads();

    // 8 nibbles -> one u32 word; coalesced 512B store per block.
    if (tid < 128) {
        unsigned int wrd = 0u;
#pragma unroll
        for (int j = 0; j < 8; j++)
            wrd |= s_nib[8 * tid + j] << (4 * j);
        tsw[tid] = wrd;
    }

#pragma unroll
    for (int o = 16; o; o >>= 1) {
        pm  += __shfl_down_sync(0xffffffffu, pm,  o);
        ps  += __shfl_down_sync(0xffffffffu, ps,  o);
        mc  += __shfl_down_sync(0xffffffffu, mc,  o);
        eqc += __shfl_down_sync(0xffffffffu, eqc, o);
    }
    __shared__ float    s_pm[8], s_ps[8];
    __shared__ unsigned s_mc[8], s_eq[8];
    int w = tid >> 5, l = tid & 31;
    if (l == 0) { s_pm[w] = pm; s_ps[w] = ps; s_mc[w] = mc; s_eq[w] = eqc; }
    __syncthreads();
    if (tid == 0) {
#pragma unroll
        for (int i = 1; i < 8; i++) { pm += s_pm[i]; ps += s_ps[i]; mc += s_mc[i]; eqc += s_eq[i]; }
        atomicAdd(&g_pm[bc], (double)pm);
        atomicAdd(&g_p [bc], (double)ps);
        atomicAdd(&g_m [bc], mc);
        atomicAdd(&g_eq[bc], eqc);
    }
}

// ---------------------------------------------------------------------------
// Pass 2: bit-sliced sobel edge count + fused finalize (threadfence ticket).
// grid = (48, 12): blockIdx.x = hg*8 + zc  (6 h-groups of 32, 8 z-chunks of 8)
// 192 threads: tid = hl*6 + ww. Software-pipelined: raw loads for z+2 issue at
// the TOP of each iteration; the bit-plane combine happens at the bottom, so
// the L2 latency is covered by the ~100-op ALU body. Last block (ticket)
// computes the loss, writes d_out, resets accumulators (replay-deterministic).
// ---------------------------------------------------------------------------
__global__ __launch_bounds__(192) void pass2(float* __restrict__ res) {
    const int bc = blockIdx.y;
    const int hg = blockIdx.x >> 3;       // 0..5
    const int zc = blockIdx.x & 7;        // 0..7
    const int tid = threadIdx.x;
    const int ww = tid % 6;
    const int hl = tid / 6;               // 0..31
    const int h  = hg * 32 + hl;
    const unsigned int* __restrict__ ts = g_tsb + (size_t)bc * (VOX / 32);

    const int hm = (h > 0)      ? h - 1 : 0;
    const int hp = (h < Hd - 1) ? h + 1 : Hd - 1;
    const int om = hm * WPR + ww, oh = h * WPR + ww, op = hp * WPR + ww;
    const bool hasL = (ww > 0), hasR = (ww < 5);

    // raw 9-word fetch for z-row (3 own rows + 3 left-neighbor + 3 right-neighbor)
    auto load_raw = [&](int z, unsigned R[9]) {
        const unsigned int* r = ts + (size_t)z * (Hd * WPR);
        R[0] = r[om]; R[1] = r[oh]; R[2] = r[op];
        if (hasL) { R[3] = r[om - 1]; R[4] = r[oh - 1]; R[5] = r[op - 1]; }
        if (hasR) { R[6] = r[om + 1]; R[7] = r[oh + 1]; R[8] = r[op + 1]; }
    };
    // combine raw words -> h-smoothed bit planes (a+2b+c, max 4) + boundary zsums
    auto combine = [&](const unsigned R[9], unsigned& p0, unsigned& p1,
                       unsigned& p2, int& sl, int& sr) {
        unsigned q = R[0] & R[2];
        p0 = R[0] ^ R[2];
        p1 = q ^ R[1];
        p2 = q & R[1];
        sl = hasL ? (int)(R[3] >> 31) + 2 * (int)(R[4] >> 31) + (int)(R[5] >> 31) : 0;
        sr = hasR ? (int)(R[6] & 1u) + 2 * (int)(R[7] & 1u) + (int)(R[8] & 1u) : 0;
    };

    const int z0 = zc * ZCH;
    unsigned A0, A1, A2, B0, B1, B2, C0, C1, C2;
    int aL, aR, bL, bR, cL, cR;
    {
        unsigned RA[9] = {0}, RB[9] = {0}, RC[9] = {0};
        load_raw((z0 > 0) ? z0 - 1 : 0, RA);   // z reflect at front
        load_raw(z0, RB);
        load_raw(z0 + 1, RC);                  // z0<=56 -> z0+1<=57 < 64
        combine(RA, A0, A1, A2, aL, aR);
        combine(RB, B0, B1, B2, bL, bR);
        combine(RC, C0, C1, C2, cL, cR);
    }

    unsigned cnt = 0;

#pragma unroll
    for (int i = 0; i < ZCH; i++) {
        const int z = z0 + i;
        // issue next-row loads FIRST (z+2, clamped = symmetric reflect at back)
        int zn = z + 2; if (zn > Zd - 1) zn = Zd - 1;
        unsigned RN[9] = {0};
        load_raw(zn, RN);

        // S = A + 2B + C  (bit-sliced, 5 planes, max 16)
        unsigned k, t0, t1, t2, t3, S0, S1, S2, S3, S4;
        t0 = A0 ^ C0;              k = A0 & C0;
        t1 = A1 ^ C1 ^ k;          k = (A1 & C1) | (k & (A1 ^ C1));
        t2 = A2 ^ C2 ^ k;          k = (A2 & C2) | (k & (A2 ^ C2));
        t3 = k;
        S0 = t0;
        S1 = t1 ^ B0;              k = t1 & B0;
        S2 = t2 ^ B1 ^ k;          k = (t2 & B1) | (k & (t2 ^ B1));
        S3 = t3 ^ B2 ^ k;          k = (t3 & B2) | (k & (t3 ^ B2));
        S4 = k;
        // scalar boundary zsums
        const int SL = aL + 2 * bL + cL;   // zsum at bit31 of word ww-1
        const int SR = aR + 2 * bR + cR;   // zsum at bit0  of word ww+1

        // X = S at w+1, Y = S at w-1 (per bit position)
        unsigned X0, X1, X2, X3, X4, Y0, Y1, Y2, Y3, Y4;
        if (hasR) {
            X0 = (S0 >> 1) | (((unsigned)(SR      & 1)) << 31);
            X1 = (S1 >> 1) | (((unsigned)((SR >> 1) & 1)) << 31);
            X2 = (S2 >> 1) | (((unsigned)((SR >> 2) & 1)) << 31);
            X3 = (S3 >> 1) | (((unsigned)((SR >> 3) & 1)) << 31);
            X4 = (S4 >> 1) | (((unsigned)((SR >> 4) & 1)) << 31);
        } else {   // global right edge: wp clamps to 191 (own bit 31)
            X0 = (S0 >> 1) | (S0 & 0x80000000u);
            X1 = (S1 >> 1) | (S1 & 0x80000000u);
            X2 = (S2 >> 1) | (S2 & 0x80000000u);
            X3 = (S3 >> 1) | (S3 & 0x80000000u);
            X4 = (S4 >> 1) | (S4 & 0x80000000u);
        }
        if (hasL) {
            Y0 = (S0 << 1) | ((unsigned)(SL      & 1));
            Y1 = (S1 << 1) | ((unsigned)((SL >> 1) & 1));
            Y2 = (S2 << 1) | ((unsigned)((SL >> 2) & 1));
            Y3 = (S3 << 1) | ((unsigned)((SL >> 3) & 1));
            Y4 = (S4 << 1) | ((unsigned)((SL >> 4) & 1));
        } else {   // global left edge: wm clamps to 0 (own bit 0)
            Y0 = (S0 << 1) | (S0 & 1u);
            Y1 = (S1 << 1) | (S1 & 1u);
            Y2 = (S2 << 1) | (S2 & 1u);
            Y3 = (S3 << 1) | (S3 & 1u);
            Y4 = (S4 << 1) | (S4 & 1u);
        }

        // bit-sliced 5-bit compare: g = (X > Y) per position
        unsigned e, g;
        e = ~(X4 ^ Y4);            g = X4 & ~Y4;
        g |= e & (X3 & ~Y3);       e &= ~(X3 ^ Y3);
        g |= e & (X2 & ~Y2);       e &= ~(X2 ^ Y2);
        g |= e & (X1 & ~Y1);       e &= ~(X1 ^ Y1);
        g |= e & (X0 & ~Y0);
        cnt += __popc(g);

        // roll z-window; combine the (by now landed) raw loads into C
        A0 = B0; A1 = B1; A2 = B2; aL = bL; aR = bR;
        B0 = C0; B1 = C1; B2 = C2; bL = cL; bR = cR;
        combine(RN, C0, C1, C2, cL, cR);
    }

#pragma unroll
    for (int o = 16; o; o >>= 1) cnt += __shfl_down_sync(0xffffffffu, cnt, o);
    __shared__ unsigned s_c[6];
    int wid = tid >> 5, l = tid & 31;
    if (l == 0) s_c[wid] = cnt;
    __syncthreads();

    // Block contribution + completion ticket. Last block finalizes.
    __shared__ bool s_last;
    if (tid == 0) {
        unsigned t = 0;
#pragma unroll
        for (int i = 0; i < 6; i++) t += s_c[i];
        atomicAdd(&g_ed[bc], t);
        __threadfence();                           // order g_ed before ticket
        unsigned rank = atomicAdd(&g_ticket, 1u);
        s_last = (rank == P2_BLOCKS - 1);
    }
    __syncthreads();
    if (!s_last || tid != 0) return;

    // ---- finalize (single thread of the last block) ----
    __threadfence();                               // acquire all g_* writes
    double loss = 0.0;
    for (int b = 0; b < Bn; b++) {
        double f[Cn];
        for (int c = 0; c < Cn; c++) f[c] = (double)g_m[b * Cn + c] / (double)VOX;
        double mn = fmin(f[0], fmin(f[1], f[2]));
        double mx = fmax(f[0], fmax(f[1], f[2]));
        double med = f[0] + f[1] + f[2] - mn - mx;   // median of 3
        double w0 = 2.0 * med / (mn + 1e-05);
        double nom = 0.0, den = 0.0;
        for (int c = 0; c < Cn; c++) {
            int i = b * Cn + c;
            double cw = (double)g_eq[i] * med / (f[c] + 1e-05) + w0 * (double)g_ed[i];
            double p1 = g_pm[i];
            double p2 = g_p[i] + (double)g_m[i];
            nom += cw * p1;
            den += cw * p2 + 1e-07;
        }
        loss += 1.0 - 2.0 * nom / den;
    }
    res[0] = (float)(loss / (double)Bn);

    // reset for next graph replay (deterministic)
#pragma unroll
    for (int i = 0; i < BC; i++) {
        g_pm[i] = 0.0; g_p[i] = 0.0; g_m[i] = 0u; g_eq[i] = 0u; g_ed[i] = 0u;
    }
    g_ticket = 0u;
}

extern "C" void kernel_launch(void* const* d_in, const int* in_sizes, int n_in,
                              void* d_out, int out_size) {
    const float* outp = (const float*)d_in[0];
    const float* mskp = (const float*)d_in[1];
    const float* thr  = (const float*)d_in[2];
    float* res = (float*)d_out;

    pass1<<<dim3(576, BC), 256>>>(outp, mskp, thr);
    pass2<<<dim3(48, BC), 192>>>(res);
}